// round 16
// baseline (speedup 1.0000x reference)
#include <cuda_runtime.h>
#include <cstdint>

#define N_NODES_C 100000
#define N_EDGES_C 300000
#define D_EMB     128
#define D_HID     64
#define N_HEADS   8
#define MAX_COMP  50000

// ---------------- scratch ----------------
__device__ float g_edata [(size_t)N_EDGES_C * D_HID];
__device__ float g_nodec [(size_t)MAX_COMP * N_HEADS * D_HID];
__device__ float g_gate  [N_HEADS];
__device__ int   g_flag  [N_NODES_C];
__device__ int   g_cidx  [N_NODES_C];
__device__ int   g_deg   [MAX_COMP];
__device__ int   g_mult  [MAX_COMP];
__device__ int   g_rowptr[MAX_COMP];
__device__ int   g_cursor[MAX_COMP];
__device__ int   g_csr   [N_EDGES_C];
__device__ int   g_act   [N_EDGES_C];
__device__ int   g_nact;
__device__ int   g_ncomp;
__device__ int   g_total;

// ---------------- tf32 helpers ----------------
__device__ __forceinline__ uint32_t to_tf32(float x) {
    uint32_t r;
    asm("cvt.rna.tf32.f32 %0, %1;" : "=r"(r) : "f"(x));
    return r;
}
// hi + lo split for 3xTF32
__device__ __forceinline__ void tf32_split(float x, uint32_t& hi, uint32_t& lo) {
    hi = to_tf32(x);
    float rem = x - __uint_as_float(hi);
    lo = to_tf32(rem);
}
__device__ __forceinline__ void mma_tf32(float* c, const uint32_t* a, const uint32_t* b) {
    asm volatile(
        "mma.sync.aligned.m16n8k8.row.col.f32.tf32.tf32.f32 "
        "{%0,%1,%2,%3}, {%4,%5,%6,%7}, {%8,%9}, {%0,%1,%2,%3};"
        : "+f"(c[0]), "+f"(c[1]), "+f"(c[2]), "+f"(c[3])
        : "r"(a[0]), "r"(a[1]), "r"(a[2]), "r"(a[3]), "r"(b[0]), "r"(b[1]));
}

// =======================================================================
// K0 chain (R11/R14 structure)
extern "C" __global__ void k0a_flags(const int* __restrict__ bn, int B)
{
    int b = blockIdx.x * blockDim.x + threadIdx.x;
    if (b < B) atomicAdd(&g_flag[bn[b]], 1);
}
extern "C" __global__ void k0b_cidx(int N)
{
    int n = blockIdx.x * blockDim.x + threadIdx.x;
    if (n >= N) return;
    int m = g_flag[n];
    if (m > 0) {
        int c = atomicAdd(&g_ncomp, 1);
        g_cidx[n] = c;
        g_mult[c] = m;
    }
}
extern "C" __global__ void k0c_compact(const int* __restrict__ edst, int E)
{
    int e = blockIdx.x * blockDim.x + threadIdx.x;
    if (e >= E) return;
    int dst = edst[e];
    if (g_flag[dst] > 0) {
        int p = atomicAdd(&g_nact, 1);
        g_act[p] = e;
        atomicAdd(&g_deg[g_cidx[dst]], 1);
    }
}
extern "C" __global__ void k0d_rowptr()
{
    int c = blockIdx.x * blockDim.x + threadIdx.x;
    if (c >= g_ncomp) return;
    int s = atomicAdd(&g_total, g_deg[c]);
    g_rowptr[c] = s;
    g_cursor[c] = s;
}
extern "C" __global__ void k0e_fill(const int* __restrict__ edst)
{
    int i = blockIdx.x * blockDim.x + threadIdx.x;
    if (i >= g_nact) return;
    int e = g_act[i];
    int c = g_cidx[edst[e]];
    int pos = atomicAdd(&g_cursor[c], 1);
    g_csr[pos] = e;
}

// =======================================================================
// K1: edata GEMM via warp-level mma.sync tf32 (3xTF32 split).
// Block: 128 edges, 8 warps; warp w owns m16 tile rows [w*16, w*16+16).
// A = s [128 x 256] f32 in smem (stride 260), B = [Wi|Wp] [64 x 256].
// D[m][n] = sum_k A[m][k] * B[n][k]  (B col-major fragment = W row n).
// =======================================================================
#define K1_AS 260                         // f32 stride (pad 4 -> conflict-free frags)
#define K1_SMEM ((128 * K1_AS + 64 * K1_AS) * 4)   // 199,680 bytes

extern "C" __global__ void __launch_bounds__(256, 1)
k1_edata(const int* __restrict__ mi, const float* __restrict__ feat,
         const float* __restrict__ Wi, const float* __restrict__ Wp)
{
    int cnt = g_nact;
    long ebase = (long)blockIdx.x * 128;
    if (ebase >= cnt) return;

    extern __shared__ float smem[];
    float* sA = smem;                     // [128][260]
    float* sB = smem + 128 * K1_AS;       // [64][260]

    int tid = threadIdx.x, warp = tid >> 5, lane = tid & 31;

    // ---- stage B = [W_i | W_p] (64 x 256 f32) ----
    for (int i = tid; i < 64 * 64; i += 256) {
        int d = i >> 6, c4 = (i & 63) * 4;
        const float* src = (c4 < 128) ? (Wi + d * 128 + c4) : (Wp + d * 128 + (c4 - 128));
        *(float4*)(sB + d * K1_AS + c4) = *(const float4*)src;
    }

    // ---- gather + stage A = s rows (128 x 256 f32) ----
    #pragma unroll 2
    for (int t = 0; t < 16; t++) {
        int row = warp * 16 + t;
        long i = ebase + row;
        int e = (i < cnt) ? g_act[i] : -1;
        float4 si = make_float4(0.f, 0.f, 0.f, 0.f), sp = si;
        if (e >= 0) {
            int4 idx = *(const int4*)(mi + (long)e * 4);
            float4 a = ((const float4*)(feat + (long)idx.x * 128))[lane];
            float4 b = ((const float4*)(feat + (long)idx.y * 128))[lane];
            float4 c = ((const float4*)(feat + (long)idx.z * 128))[lane];
            float4 d4 = ((const float4*)(feat + (long)idx.w * 128))[lane];
            si.x = a.x + d4.x; si.y = a.y + d4.y; si.z = a.z + d4.z; si.w = a.w + d4.w;
            sp.x = b.x + c.x;  sp.y = b.y + c.y;  sp.z = b.z + c.z;  sp.w = b.w + c.w;
        }
        *(float4*)(sA + row * K1_AS + lane * 4)       = si;
        *(float4*)(sA + row * K1_AS + 128 + lane * 4) = sp;
    }
    __syncthreads();

    // ---- mainloop: 8 n-tiles x 32 k8-steps, 3xTF32 ----
    int gid = lane >> 2, tig = lane & 3;
    int mbase = warp * 16;
    const float* aRow0 = sA + (mbase + gid) * K1_AS;
    const float* aRow1 = aRow0 + 8 * K1_AS;

    float c[8][4];
    #pragma unroll
    for (int nt = 0; nt < 8; nt++)
        #pragma unroll
        for (int q = 0; q < 4; q++) c[nt][q] = 0.f;

    #pragma unroll 2
    for (int ks = 0; ks < 32; ks++) {
        int k0 = ks * 8;
        // A fragment: a0=(gid,tig) a1=(gid+8,tig) a2=(gid,tig+4) a3=(gid+8,tig+4)
        uint32_t ahi[4], alo[4];
        tf32_split(aRow0[k0 + tig],     ahi[0], alo[0]);
        tf32_split(aRow1[k0 + tig],     ahi[1], alo[1]);
        tf32_split(aRow0[k0 + tig + 4], ahi[2], alo[2]);
        tf32_split(aRow1[k0 + tig + 4], ahi[3], alo[3]);

        #pragma unroll
        for (int nt = 0; nt < 8; nt++) {
            // B fragment (col-major k x n): b0=(k=tig, n=gid), b1=(k=tig+4, n=gid)
            const float* bRow = sB + (nt * 8 + gid) * K1_AS;
            uint32_t bhi[2], blo[2];
            tf32_split(bRow[k0 + tig],     bhi[0], blo[0]);
            tf32_split(bRow[k0 + tig + 4], bhi[1], blo[1]);
            mma_tf32(c[nt], ahi, bhi);
            mma_tf32(c[nt], ahi, blo);
            mma_tf32(c[nt], alo, bhi);
        }
    }

    // ---- epilogue: D rows mbase+gid (c0,c1) and mbase+gid+8 (c2,c3) ----
    long i0 = ebase + mbase + gid;
    long i1 = i0 + 8;
    int e0 = (i0 < cnt) ? g_act[i0] : -1;
    int e1 = (i1 < cnt) ? g_act[i1] : -1;
    if (e0 >= 0) {
        float* dst = g_edata + (long)e0 * 64;
        #pragma unroll
        for (int nt = 0; nt < 8; nt++)
            *(float2*)(dst + nt * 8 + 2 * tig) = make_float2(c[nt][0], c[nt][1]);
    }
    if (e1 >= 0) {
        float* dst = g_edata + (long)e1 * 64;
        #pragma unroll
        for (int nt = 0; nt < 8; nt++)
            *(float2*)(dst + nt * 8 + 2 * tig) = make_float2(c[nt][2], c[nt][3]);
    }
}

// =======================================================================
// K4csr: warp per compact node; inline logits+exp from edata row,
// single-pass den + raw sum, normalize, write nodec, fused gate.
// =======================================================================
extern "C" __global__ void k4_csr(const float* __restrict__ attn,
                                  const float* __restrict__ Wth,
                                  const float* __restrict__ Wg)
{
    __shared__ float sG[N_HEADS];
    int tid = threadIdx.x;
    if (tid < N_HEADS) sG[tid] = 0.f;
    __syncthreads();

    int gw = (blockIdx.x * blockDim.x + tid) >> 5;
    int lane = tid & 31;
    int ncomp = g_ncomp;

    if (gw < ncomp) {
        int start = g_rowptr[gw];
        int deg   = g_deg[gw];

        float aA0[N_HEADS], aA1[N_HEADS];
        #pragma unroll
        for (int h = 0; h < N_HEADS; h++) {
            aA0[h] = __ldg(attn + h * 64 + lane);
            aA1[h] = __ldg(attn + h * 64 + 32 + lane);
        }
        float wth[N_HEADS];
        #pragma unroll
        for (int h = 0; h < N_HEADS; h++)
            wth[h] = (lane < 8) ? __ldg(Wth + lane * 8 + h) : 0.f;

        float den = 0.f;
        float acc[16];
        #pragma unroll
        for (int k = 0; k < 16; k++) acc[k] = 0.f;

        for (int j = 0; j < deg; j++) {
            int e = g_csr[start + j];
            float e0 = g_edata[(long)e * 64 + lane];
            float e1 = g_edata[(long)e * 64 + lane + 32];

            float t[N_HEADS];
            #pragma unroll
            for (int h = 0; h < N_HEADS; h++) {
                float v = e0 * aA0[h] + e1 * aA1[h];
                #pragma unroll
                for (int o = 16; o > 0; o >>= 1)
                    v += __shfl_xor_sync(0xffffffffu, v, o);
                t[h] = v;
            }
            float ex = 0.f;
            if (lane < 8) {
                float x = 0.f;
                #pragma unroll
                for (int h = 0; h < N_HEADS; h++) x += t[h] * wth[h];
                x = (x > 0.f) ? x : 0.01f * x;
                ex = __expf(x);
            }
            den += ex;
            #pragma unroll
            for (int h = 0; h < N_HEADS; h++) {
                float a = __shfl_sync(0xffffffffu, ex, h);
                acc[2*h]     += a * e0;
                acc[2*h + 1] += a * e1;
            }
        }

        float rden = (lane < 8 && den != 0.f) ? (1.0f / den) : 0.f;
        #pragma unroll
        for (int h = 0; h < N_HEADS; h++) {
            float r = __shfl_sync(0xffffffffu, rden, h);
            acc[2*h]     *= r;
            acc[2*h + 1] *= r;
        }

        float* nf = g_nodec + (long)gw * 512;
        #pragma unroll
        for (int h = 0; h < N_HEADS; h++) {
            nf[h * 64 + lane]      = acc[2*h];
            nf[h * 64 + 32 + lane] = acc[2*h + 1];
        }

        float wg0 = __ldg(Wg + lane);
        float wg1 = __ldg(Wg + lane + 32);
        float m = (float)g_mult[gw];
        #pragma unroll
        for (int h = 0; h < N_HEADS; h++) {
            float v = acc[2*h] * wg0 + acc[2*h + 1] * wg1;
            #pragma unroll
            for (int o = 16; o > 0; o >>= 1)
                v += __shfl_xor_sync(0xffffffffu, v, o);
            if (lane == 0) atomicAdd(&sG[h], m * v);
        }
    }

    __syncthreads();
    if (tid < N_HEADS) atomicAdd(&g_gate[tid], sG[tid]);
}

// =======================================================================
// K6: out = nodec[cidx[bn[b]]] * (gate[h]/B + b_gate)
// =======================================================================
extern "C" __global__ void k6_out(const int* __restrict__ bn,
                                  const float* __restrict__ bg,
                                  float* __restrict__ out, int B)
{
    long gid = (long)blockIdx.x * blockDim.x + threadIdx.x;
    if (gid >= (long)B * 128) return;
    int b = (int)(gid >> 7);
    int rem = ((int)gid & 127) << 2;
    int h = rem >> 6;
    float g = g_gate[h] * (1.0f / (float)B) + bg[0];
    int c = g_cidx[bn[b]];
    const float4 v = *(const float4*)(g_nodec + (long)c * 512 + rem);
    float4 o = make_float4(v.x * g, v.y * g, v.z * g, v.w * g);
    *(float4*)(out + (long)b * 512 + rem) = o;
}

// =======================================================================
extern "C" void kernel_launch(void* const* d_in, const int* in_sizes, int n_in,
                              void* d_out, int out_size)
{
    const int*   bn   = (const int*)  d_in[0];
    const int*   mi   = (const int*)  d_in[1];
    const int*   edst = (const int*)  d_in[2];
    const float* feat = (const float*)d_in[3];
    const float* Wi   = (const float*)d_in[4];
    const float* Wp   = (const float*)d_in[5];
    const float* attn = (const float*)d_in[6];
    const float* Wth  = (const float*)d_in[7];
    const float* Wg   = (const float*)d_in[8];
    const float* bg   = (const float*)d_in[9];

    int B = in_sizes[0];
    int E = in_sizes[2];

    void* p;
    cudaGetSymbolAddress(&p, g_gate);
    cudaMemsetAsync(p, 0, sizeof(float) * N_HEADS);
    cudaGetSymbolAddress(&p, g_flag);
    cudaMemsetAsync(p, 0, sizeof(int) * N_NODES_C);
    cudaGetSymbolAddress(&p, g_deg);
    cudaMemsetAsync(p, 0, sizeof(int) * MAX_COMP);
    cudaGetSymbolAddress(&p, g_nact);
    cudaMemsetAsync(p, 0, sizeof(int));
    cudaGetSymbolAddress(&p, g_ncomp);
    cudaMemsetAsync(p, 0, sizeof(int));
    cudaGetSymbolAddress(&p, g_total);
    cudaMemsetAsync(p, 0, sizeof(int));

    k0a_flags  <<<(B + 255) / 256, 256>>>(bn, B);
    k0b_cidx   <<<(N_NODES_C + 255) / 256, 256>>>(N_NODES_C);
    k0c_compact<<<(E + 255) / 256, 256>>>(edst, E);
    k0d_rowptr <<<(MAX_COMP + 255) / 256, 256>>>();
    k0e_fill   <<<(E + 255) / 256, 256>>>(edst);

    cudaFuncSetAttribute(k1_edata, cudaFuncAttributeMaxDynamicSharedMemorySize, K1_SMEM);
    int blocks1 = (E + 127) / 128;
    k1_edata<<<blocks1, 256, K1_SMEM>>>(mi, feat, Wi, Wp);

    long k4threads = (long)MAX_COMP * 32;
    k4_csr<<<(int)((k4threads + 255) / 256), 256>>>(attn, Wth, Wg);

    long k6threads = (long)B * 128;
    k6_out<<<(int)((k6threads + 255) / 256), 256>>>(bn, bg, (float*)d_out, B);
}